// round 15
// baseline (speedup 1.0000x reference)
#include <cuda_runtime.h>

#define NN 1024
#define HH 32
typedef unsigned long long u64;
typedef unsigned int u32;

// ---- scratch (no allocations allowed) ----
__device__ float g_h1[NN * HH];                 // GRU1 final hidden per row
__device__ __align__(16) float4 g_gi2[NN * HH]; // packed pre-scaled GRU2 input gates {r,z,n,0}
__device__ float g_h2[HH];                      // GRU2 final hidden
__device__ float g_y[NN];                       // pre-softmax logits
__device__ int   g_flag = 0;                    // GRU2-done flag
__device__ int   g_cnt  = 0;                    // mlp completion counter

// ---- packed f32x2 helpers (sm_100+) ----
__device__ __forceinline__ u64 fma2(u64 a, u64 b, u64 c) {
    u64 d; asm("fma.rn.f32x2 %0, %1, %2, %3;" : "=l"(d) : "l"(a), "l"(b), "l"(c)); return d;
}
__device__ __forceinline__ u64 add2(u64 a, u64 b) {
    u64 d; asm("add.rn.f32x2 %0, %1, %2;" : "=l"(d) : "l"(a), "l"(b)); return d;
}
__device__ __forceinline__ float hadd2(u64 v) {
    float lo, hi; asm("mov.b64 {%0, %1}, %2;" : "=f"(lo), "=f"(hi) : "l"(v)); return lo + hi;
}
__device__ __forceinline__ u64 pack2(float lo, float hi) {
    u64 d; asm("mov.b64 %0, {%1, %2};" : "=l"(d) : "f"(lo), "f"(hi)); return d;
}
__device__ __forceinline__ float tanh_ap(float x) {
    float y; asm("tanh.approx.f32 %0, %1;" : "=f"(y) : "f"(x)); return y;
}
__device__ __forceinline__ u32 smaddr(const void* p) {
    u32 a; asm("{.reg .u64 t; cvta.to.shared.u64 t, %1; cvt.u32.u64 %0, t;}" : "=r"(a) : "l"(p));
    return a;
}
__device__ __forceinline__ void sts_f32(u32 a, float v) {
    asm volatile("st.shared.f32 [%0], %1;" :: "r"(a), "f"(v) : "memory");
}
__device__ __forceinline__ ulonglong2 lds_v2u64(u32 a) {
    ulonglong2 r;
    asm volatile("ld.shared.v2.u64 {%0, %1}, [%2];" : "=l"(r.x), "=l"(r.y) : "r"(a) : "memory");
    return r;
}

// activation forms (scales folded into weights at setup):
//   sigmoid(x) = 0.5 + 0.5*tanh(x/2) -> accumulate x' = 0.5*x (r, z gates)
//   n          = tanh(v)             -> accumulate v at scale 1 (n gate)
#define SRZ 0.5f

// one GRU step — R5 schedule (12 accums, 4-deep, tail adds). Best measured for K1.
__device__ __forceinline__ float gru_step(
    u32 abuf, float h, float ar_s, float az_s, float an_s, float bn_h,
    const u64* Wr, const u64* Wz, const u64* Wn, int lane)
{
    sts_f32(abuf + (lane << 2), h);
    ulonglong2 hA = lds_v2u64(abuf);
    ulonglong2 hB = lds_v2u64(abuf + 16);
    ulonglong2 hC = lds_v2u64(abuf + 32);
    ulonglong2 hD = lds_v2u64(abuf + 48);
    ulonglong2 hE = lds_v2u64(abuf + 64);
    ulonglong2 hF = lds_v2u64(abuf + 80);
    ulonglong2 hG = lds_v2u64(abuf + 96);
    ulonglong2 hH = lds_v2u64(abuf + 112);

    u64 r0, r1, r2, r3, z0, z1, z2, z3, n0, n1, n2, n3;
    r0 = fma2(Wr[0], hA.x, 0);  r1 = fma2(Wr[1], hA.y, 0);
    r2 = fma2(Wr[2], hB.x, 0);  r3 = fma2(Wr[3], hB.y, 0);
    z0 = fma2(Wz[0], hA.x, 0);  z1 = fma2(Wz[1], hA.y, 0);
    z2 = fma2(Wz[2], hB.x, 0);  z3 = fma2(Wz[3], hB.y, 0);
    n0 = fma2(Wn[0], hA.x, 0);  n1 = fma2(Wn[1], hA.y, 0);
    n2 = fma2(Wn[2], hB.x, 0);  n3 = fma2(Wn[3], hB.y, 0);

    r0 = fma2(Wr[4], hC.x, r0); r1 = fma2(Wr[5], hC.y, r1);
    r2 = fma2(Wr[6], hD.x, r2); r3 = fma2(Wr[7], hD.y, r3);
    z0 = fma2(Wz[4], hC.x, z0); z1 = fma2(Wz[5], hC.y, z1);
    z2 = fma2(Wz[6], hD.x, z2); z3 = fma2(Wz[7], hD.y, z3);
    n0 = fma2(Wn[4], hC.x, n0); n1 = fma2(Wn[5], hC.y, n1);
    n2 = fma2(Wn[6], hD.x, n2); n3 = fma2(Wn[7], hD.y, n3);

    r0 = fma2(Wr[8], hE.x, r0);  r1 = fma2(Wr[9], hE.y, r1);
    r2 = fma2(Wr[10], hF.x, r2); r3 = fma2(Wr[11], hF.y, r3);
    z0 = fma2(Wz[8], hE.x, z0);  z1 = fma2(Wz[9], hE.y, z1);
    z2 = fma2(Wz[10], hF.x, z2); z3 = fma2(Wz[11], hF.y, z3);
    n0 = fma2(Wn[8], hE.x, n0);  n1 = fma2(Wn[9], hE.y, n1);
    n2 = fma2(Wn[10], hF.x, n2); n3 = fma2(Wn[11], hF.y, n3);

    r0 = fma2(Wr[12], hG.x, r0); r1 = fma2(Wr[13], hG.y, r1);
    r2 = fma2(Wr[14], hH.x, r2); r3 = fma2(Wr[15], hH.y, r3);
    z0 = fma2(Wz[12], hG.x, z0); z1 = fma2(Wz[13], hG.y, z1);
    z2 = fma2(Wz[14], hH.x, z2); z3 = fma2(Wz[15], hH.y, z3);
    n0 = fma2(Wn[12], hG.x, n0); n1 = fma2(Wn[13], hG.y, n1);
    n2 = fma2(Wn[14], hH.x, n2); n3 = fma2(Wn[15], hH.y, n3);

    float ar = ar_s + hadd2(add2(add2(r0, r1), add2(r2, r3)));
    float az = az_s + hadd2(add2(add2(z0, z1), add2(z2, z3)));
    float hn = bn_h + hadd2(add2(add2(n0, n1), add2(n2, n3)));

    float r  = fmaf(0.5f, tanh_ap(ar), 0.5f);        // sigmoid via tanh
    float z  = fmaf(0.5f, tanh_ap(az), 0.5f);        // sigmoid via tanh
    float nn = tanh_ap(fmaf(r, hn, an_s));           // n gate
    return fmaf(z, h - nn, nn);                      // (1-z)*n + z*h
}

// ============================================================
// K1: GRU1, warp-per-row, 148 CTAs x 7 warps (R5 structure)
// ============================================================
__global__ void __launch_bounds__(224, 1) k_gru1(
    const float* __restrict__ x,
    const float* __restrict__ l1W, const float* __restrict__ l1b,
    const float* __restrict__ Wih, const float* __restrict__ Whh,
    const float* __restrict__ bih, const float* __restrict__ bhh,
    const float* __restrict__ Wih2, const float* __restrict__ bih2,
    const float* __restrict__ bhh2)
{
    __shared__ __align__(16) float sh[7][2][32];
    const int warp = threadIdx.x >> 5;
    const int lane = threadIdx.x & 31;
    const int row  = blockIdx.x * 7 + warp;
    if (row >= NN) return;

    u64 Wr[16], Wz[16], Wn[16];
    {
        const float2* wr = (const float2*)(Whh + (0 * HH + lane) * HH);
        const float2* wz = (const float2*)(Whh + (1 * HH + lane) * HH);
        const float2* wn = (const float2*)(Whh + (2 * HH + lane) * HH);
#pragma unroll
        for (int k = 0; k < 16; k++) {
            float2 a = wr[k], b = wz[k], c = wn[k];
            Wr[k] = pack2(a.x * SRZ, a.y * SRZ);
            Wz[k] = pack2(b.x * SRZ, b.y * SRZ);
            Wn[k] = pack2(c.x, c.y);
        }
    }

    // Fold l1 linear into scalar affine input gates: gi[g] = x*A[g] + B[g]
    float Ar = 0.f, Az = 0.f, An = 0.f, Br = 0.f, Bz = 0.f, Bn = 0.f;
#pragma unroll
    for (int j = 0; j < HH; j++) {
        float w = l1W[j], b = l1b[j];
        float wr_ = Wih[(0 * HH + lane) * HH + j];
        float wz_ = Wih[(1 * HH + lane) * HH + j];
        float wn_ = Wih[(2 * HH + lane) * HH + j];
        Ar = fmaf(wr_, w, Ar); Br = fmaf(wr_, b, Br);
        Az = fmaf(wz_, w, Az); Bz = fmaf(wz_, b, Bz);
        An = fmaf(wn_, w, An); Bn = fmaf(wn_, b, Bn);
    }
    Br = (Br + bih[lane]      + bhh[lane])      * SRZ;  Ar *= SRZ;
    Bz = (Bz + bih[32 + lane] + bhh[32 + lane]) * SRZ;  Az *= SRZ;
    Bn = Bn + bih[64 + lane];
    const float bn_h = bhh[64 + lane];

    const u32 shb = smaddr(&sh[warp][0][0]);
    const float* xrow = x + (size_t)row * NN;
    float h = 0.0f;
    float xc = xrow[lane];

    for (int c0 = 0; c0 < NN; c0 += 32) {
        float xcur = xc;
        if (c0 + 32 < NN) xc = xrow[c0 + 32 + lane];
#pragma unroll
        for (int k = 0; k < 32; k++) {
            float xv = __shfl_sync(0xffffffffu, xcur, k);
            float ar_s = fmaf(xv, Ar, Br);
            float az_s = fmaf(xv, Az, Bz);
            float an_s = fmaf(xv, An, Bn);
            h = gru_step(shb + ((k & 1) << 7), h, ar_s, az_s, an_s, bn_h,
                         Wr, Wz, Wn, lane);
        }
    }

    g_h1[row * HH + lane] = h;

    // GRU2 input-gate precompute for time index = row (pre-scaled, packed)
    float a0 = bih2[lane]      + bhh2[lane];
    float a1 = bih2[32 + lane] + bhh2[32 + lane];
    float a2 = bih2[64 + lane];
#pragma unroll
    for (int j = 0; j < HH; j++) {
        float hj = __shfl_sync(0xffffffffu, h, j);
        a0 = fmaf(Wih2[(0 * HH + lane) * HH + j], hj, a0);
        a1 = fmaf(Wih2[(1 * HH + lane) * HH + j], hj, a1);
        a2 = fmaf(Wih2[(2 * HH + lane) * HH + j], hj, a2);
    }
    g_gi2[row * HH + lane] = make_float4(a0 * SRZ, a1 * SRZ, a2, 0.0f);
}

// ============================================================
// K2 (fused tail): CTA0 = GRU2 single warp with SHFL-based h
// broadcast (no STS->LDS store-commit wait on the serial path);
// CTAs 1..128 = MLP overlapped with GRU2; last CTA = softmax.
// ============================================================
__global__ void __launch_bounds__(256, 1) k_tail(
    const float* __restrict__ Whh2, const float* __restrict__ bhh2,
    const float* __restrict__ f1W, const float* __restrict__ f1b,
    const float* __restrict__ f2W, const float* __restrict__ f2b,
    const float* __restrict__ f3W, const float* __restrict__ f3b,
    float* __restrict__ out)
{
    const int bid  = blockIdx.x;
    const int tid  = threadIdx.x;
    const int lane = tid & 31;

    // ---------------- CTA 0: GRU2 (shfl broadcast) ----------------
    if (bid == 0) {
        if (tid < 32) {
            u64 Wr[16], Wz[16], Wn[16];
            {
                const float2* wr = (const float2*)(Whh2 + (0 * HH + lane) * HH);
                const float2* wz = (const float2*)(Whh2 + (1 * HH + lane) * HH);
                const float2* wn = (const float2*)(Whh2 + (2 * HH + lane) * HH);
#pragma unroll
                for (int k = 0; k < 16; k++) {
                    float2 a = wr[k], b = wz[k], c = wn[k];
                    Wr[k] = pack2(a.x * SRZ, a.y * SRZ);
                    Wz[k] = pack2(b.x * SRZ, b.y * SRZ);
                    Wn[k] = pack2(c.x, c.y);
                }
            }
            const float bn_h = bhh2[64 + lane];

            float4 pg[4];
#pragma unroll
            for (int i = 0; i < 4; i++)
                pg[i] = g_gi2[i * HH + lane];

            float h = 0.0f;
#pragma unroll 4
            for (int t = 0; t < NN; t++) {
                const int s = t & 3;
                const float4 gi = pg[s];
                if (t + 4 < NN)
                    pg[s] = g_gi2[(t + 4) * HH + lane];

                // h broadcast via shfl (no smem round trip)
                u64 hp[16];
#pragma unroll
                for (int k = 0; k < 16; k++) {
                    float lo = __shfl_sync(0xffffffffu, h, 2 * k);
                    float hi = __shfl_sync(0xffffffffu, h, 2 * k + 1);
                    hp[k] = pack2(lo, hi);
                }

                // r gate (first: tanh overlaps z/n issue)
                u64 r0 = fma2(Wr[0], hp[0], 0),  r1 = fma2(Wr[1], hp[1], 0);
                u64 r2 = fma2(Wr[2], hp[2], 0),  r3 = fma2(Wr[3], hp[3], 0);
                r0 = fma2(Wr[4],  hp[4],  r0); r1 = fma2(Wr[5],  hp[5],  r1);
                r2 = fma2(Wr[6],  hp[6],  r2); r3 = fma2(Wr[7],  hp[7],  r3);
                r0 = fma2(Wr[8],  hp[8],  r0); r1 = fma2(Wr[9],  hp[9],  r1);
                r2 = fma2(Wr[10], hp[10], r2); r3 = fma2(Wr[11], hp[11], r3);
                r0 = fma2(Wr[12], hp[12], r0); r1 = fma2(Wr[13], hp[13], r1);
                r2 = fma2(Wr[14], hp[14], r2); r3 = fma2(Wr[15], hp[15], r3);
                float ar = gi.x + hadd2(add2(add2(r0, r1), add2(r2, r3)));
                float r  = fmaf(0.5f, tanh_ap(ar), 0.5f);

                // z gate
                u64 z0 = fma2(Wz[0], hp[0], 0),  z1 = fma2(Wz[1], hp[1], 0);
                u64 z2 = fma2(Wz[2], hp[2], 0),  z3 = fma2(Wz[3], hp[3], 0);
                z0 = fma2(Wz[4],  hp[4],  z0); z1 = fma2(Wz[5],  hp[5],  z1);
                z2 = fma2(Wz[6],  hp[6],  z2); z3 = fma2(Wz[7],  hp[7],  z3);
                z0 = fma2(Wz[8],  hp[8],  z0); z1 = fma2(Wz[9],  hp[9],  z1);
                z2 = fma2(Wz[10], hp[10], z2); z3 = fma2(Wz[11], hp[11], z3);
                z0 = fma2(Wz[12], hp[12], z0); z1 = fma2(Wz[13], hp[13], z1);
                z2 = fma2(Wz[14], hp[14], z2); z3 = fma2(Wz[15], hp[15], z3);
                float az = gi.y + hadd2(add2(add2(z0, z1), add2(z2, z3)));
                float z  = fmaf(0.5f, tanh_ap(az), 0.5f);

                // n gate
                u64 n0 = fma2(Wn[0], hp[0], 0),  n1 = fma2(Wn[1], hp[1], 0);
                u64 n2 = fma2(Wn[2], hp[2], 0),  n3 = fma2(Wn[3], hp[3], 0);
                n0 = fma2(Wn[4],  hp[4],  n0); n1 = fma2(Wn[5],  hp[5],  n1);
                n2 = fma2(Wn[6],  hp[6],  n2); n3 = fma2(Wn[7],  hp[7],  n3);
                n0 = fma2(Wn[8],  hp[8],  n0); n1 = fma2(Wn[9],  hp[9],  n1);
                n2 = fma2(Wn[10], hp[10], n2); n3 = fma2(Wn[11], hp[11], n3);
                n0 = fma2(Wn[12], hp[12], n0); n1 = fma2(Wn[13], hp[13], n1);
                n2 = fma2(Wn[14], hp[14], n2); n3 = fma2(Wn[15], hp[15], n3);
                float hn = bn_h + hadd2(add2(add2(n0, n1), add2(n2, n3)));
                float nn = tanh_ap(fmaf(r, hn, gi.z));

                h = fmaf(z, h - nn, nn);
            }
            g_h2[lane] = h;
        }
        __syncthreads();
        if (tid == 0) {
            __threadfence();
            atomicExch(&g_flag, 1);
        }
        return;
    }

    // ---------------- CTAs 1..128: MLP (overlapped staging) ----------------
    __shared__ float sW1[64 * 32];
    __shared__ float sW2[32 * 32];
    __shared__ float sb1[32], sb2[32], sW3[32];
    __shared__ int sLast;
    __shared__ float sred[8], sbc[2];

    const int row = (bid - 1) * 8 + (tid >> 5);

    // hl load + weight staging run WHILE gru2 executes
    float hl = g_h1[row * HH + lane];

    for (int idx = tid; idx < 2048; idx += 256) {
        int i = idx >> 6, j = idx & 63;
        sW1[j * 32 + i] = f1W[idx];
    }
    for (int idx = tid; idx < 1024; idx += 256) {
        int i = idx >> 5, j = idx & 31;
        sW2[j * 32 + i] = f2W[idx];
    }
    if (tid < 32) { sb1[tid] = f1b[tid]; sb2[tid] = f2b[tid]; sW3[tid] = f3W[tid]; }

    // layer-1 partial from hl (independent of gru2)
    float a0 = 0.f, a1 = 0.f;
    __syncthreads();
#pragma unroll
    for (int j = 0; j < 16; j++) {
        float u0 = __shfl_sync(0xffffffffu, hl, j);
        float u1 = __shfl_sync(0xffffffffu, hl, j + 16);
        a0 = fmaf(sW1[j * 32 + lane],        u0, a0);
        a1 = fmaf(sW1[(j + 16) * 32 + lane], u1, a1);
    }

    // wait for gru2
    if (tid == 0) {
        while (*((volatile int*)&g_flag) == 0) __nanosleep(64);
        __threadfence();
    }
    __syncthreads();

    float hg = g_h2[lane];
    float a2 = sb1[lane], a3 = 0.f;
#pragma unroll
    for (int j = 0; j < 16; j++) {
        float u2 = __shfl_sync(0xffffffffu, hg, j);
        float u3 = __shfl_sync(0xffffffffu, hg, j + 16);
        a2 = fmaf(sW1[(j + 32) * 32 + lane], u2, a2);
        a3 = fmaf(sW1[(j + 48) * 32 + lane], u3, a3);
    }
    float y1 = fmaxf((a0 + a1) + (a2 + a3), 0.0f);

    float b0 = sb2[lane], b1 = 0.f;
#pragma unroll
    for (int j = 0; j < 16; j++) {
        float u0 = __shfl_sync(0xffffffffu, y1, j);
        float u1 = __shfl_sync(0xffffffffu, y1, j + 16);
        b0 = fmaf(sW2[j * 32 + lane],        u0, b0);
        b1 = fmaf(sW2[(j + 16) * 32 + lane], u1, b1);
    }
    float y2 = fmaxf(b0 + b1, 0.0f);

    float p = sW3[lane] * y2;
#pragma unroll
    for (int off = 16; off; off >>= 1)
        p += __shfl_xor_sync(0xffffffffu, p, off);
    if (lane == 0) g_y[row] = p + f3b[0];

    // ---------------- last MLP CTA: softmax + reset ----------------
    __syncthreads();
    if (tid == 0) {
        __threadfence();
        int old = atomicAdd(&g_cnt, 1);
        sLast = (old == 127) ? 1 : 0;
    }
    __syncthreads();

    if (sLast) {
        __threadfence();
        const int wid = tid >> 5;
        float v[4];
        float m = -1e30f;
#pragma unroll
        for (int j = 0; j < 4; j++) {
            v[j] = g_y[tid + 256 * j];
            m = fmaxf(m, v[j]);
        }
#pragma unroll
        for (int off = 16; off; off >>= 1)
            m = fmaxf(m, __shfl_xor_sync(0xffffffffu, m, off));
        if (lane == 0) sred[wid] = m;
        __syncthreads();
        if (wid == 0) {
            float mm = (lane < 8) ? sred[lane] : -1e30f;
#pragma unroll
            for (int off = 16; off; off >>= 1)
                mm = fmaxf(mm, __shfl_xor_sync(0xffffffffu, mm, off));
            if (lane == 0) sbc[0] = mm;
        }
        __syncthreads();
        const float M = sbc[0];

        float e[4];
        float s = 0.0f;
#pragma unroll
        for (int j = 0; j < 4; j++) {
            e[j] = __expf(v[j] - M);
            s += e[j];
        }
#pragma unroll
        for (int off = 16; off; off >>= 1)
            s += __shfl_xor_sync(0xffffffffu, s, off);
        if (lane == 0) sred[wid] = s;
        __syncthreads();
        if (wid == 0) {
            float ss = (lane < 8) ? sred[lane] : 0.0f;
#pragma unroll
            for (int off = 16; off; off >>= 1)
                ss += __shfl_xor_sync(0xffffffffu, ss, off);
            if (lane == 0) sbc[1] = ss;
        }
        __syncthreads();
        const float S = sbc[1];

#pragma unroll
        for (int j = 0; j < 4; j++)
            out[tid + 256 * j] = e[j] / S;

        // reset sync state for next graph replay
        __syncthreads();
        if (tid == 0) { g_flag = 0; g_cnt = 0; }
    }
}

// ============================================================
// launch
// ============================================================
extern "C" void kernel_launch(void* const* d_in, const int* in_sizes, int n_in,
                              void* d_out, int out_size)
{
    const float* x      = (const float*)d_in[0];
    const float* l1_W   = (const float*)d_in[1];
    const float* l1_b   = (const float*)d_in[2];
    const float* g1_Wih = (const float*)d_in[3];
    const float* g1_Whh = (const float*)d_in[4];
    const float* g1_bih = (const float*)d_in[5];
    const float* g1_bhh = (const float*)d_in[6];
    const float* g2_Wih = (const float*)d_in[7];
    const float* g2_Whh = (const float*)d_in[8];
    const float* g2_bih = (const float*)d_in[9];
    const float* g2_bhh = (const float*)d_in[10];
    const float* f1_W   = (const float*)d_in[11];
    const float* f1_b   = (const float*)d_in[12];
    const float* f2_W   = (const float*)d_in[13];
    const float* f2_b   = (const float*)d_in[14];
    const float* f3_W   = (const float*)d_in[15];
    const float* f3_b   = (const float*)d_in[16];

    k_gru1<<<148, 224>>>(x, l1_W, l1_b, g1_Wih, g1_Whh, g1_bih, g1_bhh,
                         g2_Wih, g2_bih, g2_bhh);
    k_tail<<<129, 256>>>(g2_Whh, g2_bhh,
                         f1_W, f1_b, f2_W, f2_b, f3_W, f3_b,
                         (float*)d_out);
}

// round 16
// speedup vs baseline: 1.1242x; 1.1242x over previous
#include <cuda_runtime.h>

#define NN 1024
#define HH 32
typedef unsigned long long u64;
typedef unsigned int u32;

// ---- scratch (no allocations allowed) ----
__device__ float g_h1[NN * HH];                 // GRU1 final hidden per row
__device__ __align__(16) float4 g_gi2[NN * HH]; // packed pre-scaled GRU2 input gates {r,z,n,0}
__device__ float g_h2[HH];                      // GRU2 final hidden
__device__ float g_y[NN];                       // pre-softmax logits
__device__ int   g_flag = 0;                    // GRU2-done flag
__device__ int   g_cnt  = 0;                    // mlp completion counter

// ---- packed f32x2 helpers (sm_100+) ----
__device__ __forceinline__ u64 fma2(u64 a, u64 b, u64 c) {
    u64 d; asm("fma.rn.f32x2 %0, %1, %2, %3;" : "=l"(d) : "l"(a), "l"(b), "l"(c)); return d;
}
__device__ __forceinline__ u64 add2(u64 a, u64 b) {
    u64 d; asm("add.rn.f32x2 %0, %1, %2;" : "=l"(d) : "l"(a), "l"(b)); return d;
}
__device__ __forceinline__ float hadd2(u64 v) {
    float lo, hi; asm("mov.b64 {%0, %1}, %2;" : "=f"(lo), "=f"(hi) : "l"(v)); return lo + hi;
}
__device__ __forceinline__ u64 pack2(float lo, float hi) {
    u64 d; asm("mov.b64 %0, {%1, %2};" : "=l"(d) : "f"(lo), "f"(hi)); return d;
}
__device__ __forceinline__ float tanh_ap(float x) {
    float y; asm("tanh.approx.f32 %0, %1;" : "=f"(y) : "f"(x)); return y;
}
__device__ __forceinline__ u32 smaddr(const void* p) {
    u32 a; asm("{.reg .u64 t; cvta.to.shared.u64 t, %1; cvt.u32.u64 %0, t;}" : "=r"(a) : "l"(p));
    return a;
}
__device__ __forceinline__ void sts_f32(u32 a, float v) {
    asm volatile("st.shared.f32 [%0], %1;" :: "r"(a), "f"(v) : "memory");
}
__device__ __forceinline__ ulonglong2 lds_v2u64(u32 a) {
    ulonglong2 r;
    asm volatile("ld.shared.v2.u64 {%0, %1}, [%2];" : "=l"(r.x), "=l"(r.y) : "r"(a) : "memory");
    return r;
}

// activation forms (scales folded into weights at setup):
//   sigmoid(x) = 0.5 + 0.5*tanh(x/2) -> accumulate x' = 0.5*x (r, z gates)
//   n          = tanh(v)             -> accumulate v at scale 1 (n gate)
#define SRZ 0.5f

// one GRU step — R5 schedule (12 accums, 4-deep, tail adds). Best measured for K1.
__device__ __forceinline__ float gru_step(
    u32 abuf, float h, float ar_s, float az_s, float an_s, float bn_h,
    const u64* Wr, const u64* Wz, const u64* Wn, int lane)
{
    sts_f32(abuf + (lane << 2), h);
    ulonglong2 hA = lds_v2u64(abuf);
    ulonglong2 hB = lds_v2u64(abuf + 16);
    ulonglong2 hC = lds_v2u64(abuf + 32);
    ulonglong2 hD = lds_v2u64(abuf + 48);
    ulonglong2 hE = lds_v2u64(abuf + 64);
    ulonglong2 hF = lds_v2u64(abuf + 80);
    ulonglong2 hG = lds_v2u64(abuf + 96);
    ulonglong2 hH = lds_v2u64(abuf + 112);

    u64 r0, r1, r2, r3, z0, z1, z2, z3, n0, n1, n2, n3;
    r0 = fma2(Wr[0], hA.x, 0);  r1 = fma2(Wr[1], hA.y, 0);
    r2 = fma2(Wr[2], hB.x, 0);  r3 = fma2(Wr[3], hB.y, 0);
    z0 = fma2(Wz[0], hA.x, 0);  z1 = fma2(Wz[1], hA.y, 0);
    z2 = fma2(Wz[2], hB.x, 0);  z3 = fma2(Wz[3], hB.y, 0);
    n0 = fma2(Wn[0], hA.x, 0);  n1 = fma2(Wn[1], hA.y, 0);
    n2 = fma2(Wn[2], hB.x, 0);  n3 = fma2(Wn[3], hB.y, 0);

    r0 = fma2(Wr[4], hC.x, r0); r1 = fma2(Wr[5], hC.y, r1);
    r2 = fma2(Wr[6], hD.x, r2); r3 = fma2(Wr[7], hD.y, r3);
    z0 = fma2(Wz[4], hC.x, z0); z1 = fma2(Wz[5], hC.y, z1);
    z2 = fma2(Wz[6], hD.x, z2); z3 = fma2(Wz[7], hD.y, z3);
    n0 = fma2(Wn[4], hC.x, n0); n1 = fma2(Wn[5], hC.y, n1);
    n2 = fma2(Wn[6], hD.x, n2); n3 = fma2(Wn[7], hD.y, n3);

    r0 = fma2(Wr[8], hE.x, r0);  r1 = fma2(Wr[9], hE.y, r1);
    r2 = fma2(Wr[10], hF.x, r2); r3 = fma2(Wr[11], hF.y, r3);
    z0 = fma2(Wz[8], hE.x, z0);  z1 = fma2(Wz[9], hE.y, z1);
    z2 = fma2(Wz[10], hF.x, z2); z3 = fma2(Wz[11], hF.y, z3);
    n0 = fma2(Wn[8], hE.x, n0);  n1 = fma2(Wn[9], hE.y, n1);
    n2 = fma2(Wn[10], hF.x, n2); n3 = fma2(Wn[11], hF.y, n3);

    r0 = fma2(Wr[12], hG.x, r0); r1 = fma2(Wr[13], hG.y, r1);
    r2 = fma2(Wr[14], hH.x, r2); r3 = fma2(Wr[15], hH.y, r3);
    z0 = fma2(Wz[12], hG.x, z0); z1 = fma2(Wz[13], hG.y, z1);
    z2 = fma2(Wz[14], hH.x, z2); z3 = fma2(Wz[15], hH.y, z3);
    n0 = fma2(Wn[12], hG.x, n0); n1 = fma2(Wn[13], hG.y, n1);
    n2 = fma2(Wn[14], hH.x, n2); n3 = fma2(Wn[15], hH.y, n3);

    float ar = ar_s + hadd2(add2(add2(r0, r1), add2(r2, r3)));
    float az = az_s + hadd2(add2(add2(z0, z1), add2(z2, z3)));
    float hn = bn_h + hadd2(add2(add2(n0, n1), add2(n2, n3)));

    float r  = fmaf(0.5f, tanh_ap(ar), 0.5f);        // sigmoid via tanh
    float z  = fmaf(0.5f, tanh_ap(az), 0.5f);        // sigmoid via tanh
    float nn = tanh_ap(fmaf(r, hn, an_s));           // n gate
    return fmaf(z, h - nn, nn);                      // (1-z)*n + z*h
}

// ============================================================
// K1: GRU1, warp-per-row, 148 CTAs x 7 warps (R5 structure)
// ============================================================
__global__ void __launch_bounds__(224, 1) k_gru1(
    const float* __restrict__ x,
    const float* __restrict__ l1W, const float* __restrict__ l1b,
    const float* __restrict__ Wih, const float* __restrict__ Whh,
    const float* __restrict__ bih, const float* __restrict__ bhh,
    const float* __restrict__ Wih2, const float* __restrict__ bih2,
    const float* __restrict__ bhh2)
{
    __shared__ __align__(16) float sh[7][2][32];
    const int warp = threadIdx.x >> 5;
    const int lane = threadIdx.x & 31;
    const int row  = blockIdx.x * 7 + warp;
    if (row >= NN) return;

    u64 Wr[16], Wz[16], Wn[16];
    {
        const float2* wr = (const float2*)(Whh + (0 * HH + lane) * HH);
        const float2* wz = (const float2*)(Whh + (1 * HH + lane) * HH);
        const float2* wn = (const float2*)(Whh + (2 * HH + lane) * HH);
#pragma unroll
        for (int k = 0; k < 16; k++) {
            float2 a = wr[k], b = wz[k], c = wn[k];
            Wr[k] = pack2(a.x * SRZ, a.y * SRZ);
            Wz[k] = pack2(b.x * SRZ, b.y * SRZ);
            Wn[k] = pack2(c.x, c.y);
        }
    }

    // Fold l1 linear into scalar affine input gates: gi[g] = x*A[g] + B[g]
    float Ar = 0.f, Az = 0.f, An = 0.f, Br = 0.f, Bz = 0.f, Bn = 0.f;
#pragma unroll
    for (int j = 0; j < HH; j++) {
        float w = l1W[j], b = l1b[j];
        float wr_ = Wih[(0 * HH + lane) * HH + j];
        float wz_ = Wih[(1 * HH + lane) * HH + j];
        float wn_ = Wih[(2 * HH + lane) * HH + j];
        Ar = fmaf(wr_, w, Ar); Br = fmaf(wr_, b, Br);
        Az = fmaf(wz_, w, Az); Bz = fmaf(wz_, b, Bz);
        An = fmaf(wn_, w, An); Bn = fmaf(wn_, b, Bn);
    }
    Br = (Br + bih[lane]      + bhh[lane])      * SRZ;  Ar *= SRZ;
    Bz = (Bz + bih[32 + lane] + bhh[32 + lane]) * SRZ;  Az *= SRZ;
    Bn = Bn + bih[64 + lane];
    const float bn_h = bhh[64 + lane];

    const u32 shb = smaddr(&sh[warp][0][0]);
    const float* xrow = x + (size_t)row * NN;
    float h = 0.0f;
    float xc = xrow[lane];

    for (int c0 = 0; c0 < NN; c0 += 32) {
        float xcur = xc;
        if (c0 + 32 < NN) xc = xrow[c0 + 32 + lane];
#pragma unroll
        for (int k = 0; k < 32; k++) {
            float xv = __shfl_sync(0xffffffffu, xcur, k);
            float ar_s = fmaf(xv, Ar, Br);
            float az_s = fmaf(xv, Az, Bz);
            float an_s = fmaf(xv, An, Bn);
            h = gru_step(shb + ((k & 1) << 7), h, ar_s, az_s, an_s, bn_h,
                         Wr, Wz, Wn, lane);
        }
    }

    g_h1[row * HH + lane] = h;

    // GRU2 input-gate precompute for time index = row (pre-scaled, packed)
    float a0 = bih2[lane]      + bhh2[lane];
    float a1 = bih2[32 + lane] + bhh2[32 + lane];
    float a2 = bih2[64 + lane];
#pragma unroll
    for (int j = 0; j < HH; j++) {
        float hj = __shfl_sync(0xffffffffu, h, j);
        a0 = fmaf(Wih2[(0 * HH + lane) * HH + j], hj, a0);
        a1 = fmaf(Wih2[(1 * HH + lane) * HH + j], hj, a1);
        a2 = fmaf(Wih2[(2 * HH + lane) * HH + j], hj, a2);
    }
    g_gi2[row * HH + lane] = make_float4(a0 * SRZ, a1 * SRZ, a2, 0.0f);
}

// ============================================================
// K2 (fused tail): CTA0 = GRU2 (single warp, R12 schedule);
// CTAs 1..128 = MLP (weights staged + hl loaded DURING gru2,
// spin on flag); last MLP CTA = softmax + state reset.
// ============================================================
__global__ void __launch_bounds__(256, 1) k_tail(
    const float* __restrict__ Whh2, const float* __restrict__ bhh2,
    const float* __restrict__ f1W, const float* __restrict__ f1b,
    const float* __restrict__ f2W, const float* __restrict__ f2b,
    const float* __restrict__ f3W, const float* __restrict__ f3b,
    float* __restrict__ out)
{
    const int bid  = blockIdx.x;
    const int tid  = threadIdx.x;
    const int lane = tid & 31;

    // ---------------- CTA 0: GRU2 (R12 exact) ----------------
    if (bid == 0) {
        __shared__ __align__(16) float sh[2][32];
        if (tid < 32) {
            u64 Wr[16], Wz[16], Wn[16];
            {
                const float2* wr = (const float2*)(Whh2 + (0 * HH + lane) * HH);
                const float2* wz = (const float2*)(Whh2 + (1 * HH + lane) * HH);
                const float2* wn = (const float2*)(Whh2 + (2 * HH + lane) * HH);
#pragma unroll
                for (int k = 0; k < 16; k++) {
                    float2 a = wr[k], b = wz[k], c = wn[k];
                    Wr[k] = pack2(a.x * SRZ, a.y * SRZ);
                    Wz[k] = pack2(b.x * SRZ, b.y * SRZ);
                    Wn[k] = pack2(c.x, c.y);
                }
            }
            const float bn_h = bhh2[64 + lane];

            float4 pg[4];
#pragma unroll
            for (int i = 0; i < 4; i++)
                pg[i] = g_gi2[i * HH + lane];

            const u32 shb = smaddr(&sh[0][0]);
            float h = 0.0f;
#pragma unroll 4
            for (int t = 0; t < NN; t++) {
                const int s = t & 3;
                const float4 gi = pg[s];
                if (t + 4 < NN)
                    pg[s] = g_gi2[(t + 4) * HH + lane];

                const u32 ab = shb + ((t & 1) << 7);
                sts_f32(ab + (lane << 2), h);
                ulonglong2 hA = lds_v2u64(ab);
                ulonglong2 hB = lds_v2u64(ab + 16);
                ulonglong2 hC = lds_v2u64(ab + 32);
                ulonglong2 hD = lds_v2u64(ab + 48);
                ulonglong2 hE = lds_v2u64(ab + 64);
                ulonglong2 hF = lds_v2u64(ab + 80);
                ulonglong2 hG = lds_v2u64(ab + 96);
                ulonglong2 hH = lds_v2u64(ab + 112);

                // r gate
                u64 r0 = fma2(Wr[0], hA.x, 0),  r1 = fma2(Wr[1], hA.y, 0);
                u64 r2 = fma2(Wr[2], hB.x, 0),  r3 = fma2(Wr[3], hB.y, 0);
                r0 = fma2(Wr[4],  hC.x, r0); r1 = fma2(Wr[5],  hC.y, r1);
                r2 = fma2(Wr[6],  hD.x, r2); r3 = fma2(Wr[7],  hD.y, r3);
                r0 = fma2(Wr[8],  hE.x, r0); r1 = fma2(Wr[9],  hE.y, r1);
                r2 = fma2(Wr[10], hF.x, r2); r3 = fma2(Wr[11], hF.y, r3);
                r0 = fma2(Wr[12], hG.x, r0); r1 = fma2(Wr[13], hG.y, r1);
                r2 = fma2(Wr[14], hH.x, r2); r3 = fma2(Wr[15], hH.y, r3);
                float ar = gi.x + hadd2(add2(add2(r0, r1), add2(r2, r3)));
                float r  = fmaf(0.5f, tanh_ap(ar), 0.5f);

                // z gate
                u64 z0 = fma2(Wz[0], hA.x, 0),  z1 = fma2(Wz[1], hA.y, 0);
                u64 z2 = fma2(Wz[2], hB.x, 0),  z3 = fma2(Wz[3], hB.y, 0);
                z0 = fma2(Wz[4],  hC.x, z0); z1 = fma2(Wz[5],  hC.y, z1);
                z2 = fma2(Wz[6],  hD.x, z2); z3 = fma2(Wz[7],  hD.y, z3);
                z0 = fma2(Wz[8],  hE.x, z0); z1 = fma2(Wz[9],  hE.y, z1);
                z2 = fma2(Wz[10], hF.x, z2); z3 = fma2(Wz[11], hF.y, z3);
                z0 = fma2(Wz[12], hG.x, z0); z1 = fma2(Wz[13], hG.y, z1);
                z2 = fma2(Wz[14], hH.x, z2); z3 = fma2(Wz[15], hH.y, z3);
                float az = gi.y + hadd2(add2(add2(z0, z1), add2(z2, z3)));
                float z  = fmaf(0.5f, tanh_ap(az), 0.5f);

                // n gate
                u64 n0 = fma2(Wn[0], hA.x, 0),  n1 = fma2(Wn[1], hA.y, 0);
                u64 n2 = fma2(Wn[2], hB.x, 0),  n3 = fma2(Wn[3], hB.y, 0);
                n0 = fma2(Wn[4],  hC.x, n0); n1 = fma2(Wn[5],  hC.y, n1);
                n2 = fma2(Wn[6],  hD.x, n2); n3 = fma2(Wn[7],  hD.y, n3);
                n0 = fma2(Wn[8],  hE.x, n0); n1 = fma2(Wn[9],  hE.y, n1);
                n2 = fma2(Wn[10], hF.x, n2); n3 = fma2(Wn[11], hF.y, n3);
                n0 = fma2(Wn[12], hG.x, n0); n1 = fma2(Wn[13], hG.y, n1);
                n2 = fma2(Wn[14], hH.x, n2); n3 = fma2(Wn[15], hH.y, n3);
                float hn = bn_h + hadd2(add2(add2(n0, n1), add2(n2, n3)));
                float nn = tanh_ap(fmaf(r, hn, gi.z));

                h = fmaf(z, h - nn, nn);
            }
            g_h2[lane] = h;
        }
        __syncthreads();
        if (tid == 0) {
            __threadfence();
            atomicExch(&g_flag, 1);
        }
        return;
    }

    // ---------------- CTAs 1..128: MLP (overlapped staging) ----------------
    __shared__ float sW1[64 * 32];
    __shared__ float sW2[32 * 32];
    __shared__ float sb1[32], sb2[32], sW3[32];
    __shared__ int sLast;
    __shared__ float sred[8], sbc[2];

    const int row = (bid - 1) * 8 + (tid >> 5);

    // hl load + weight staging run WHILE gru2 executes
    float hl = g_h1[row * HH + lane];

    for (int idx = tid; idx < 2048; idx += 256) {
        int i = idx >> 6, j = idx & 63;
        sW1[j * 32 + i] = f1W[idx];
    }
    for (int idx = tid; idx < 1024; idx += 256) {
        int i = idx >> 5, j = idx & 31;
        sW2[j * 32 + i] = f2W[idx];
    }
    if (tid < 32) { sb1[tid] = f1b[tid]; sb2[tid] = f2b[tid]; sW3[tid] = f3W[tid]; }

    // layer-1 partial from hl (independent of gru2)
    float a0 = 0.f, a1 = 0.f;
    __syncthreads();
#pragma unroll
    for (int j = 0; j < 16; j++) {
        float u0 = __shfl_sync(0xffffffffu, hl, j);
        float u1 = __shfl_sync(0xffffffffu, hl, j + 16);
        a0 = fmaf(sW1[j * 32 + lane],        u0, a0);
        a1 = fmaf(sW1[(j + 16) * 32 + lane], u1, a1);
    }

    // wait for gru2
    if (tid == 0) {
        while (*((volatile int*)&g_flag) == 0) __nanosleep(64);
        __threadfence();
    }
    __syncthreads();

    float hg = g_h2[lane];
    float a2 = sb1[lane], a3 = 0.f;
#pragma unroll
    for (int j = 0; j < 16; j++) {
        float u2 = __shfl_sync(0xffffffffu, hg, j);
        float u3 = __shfl_sync(0xffffffffu, hg, j + 16);
        a2 = fmaf(sW1[(j + 32) * 32 + lane], u2, a2);
        a3 = fmaf(sW1[(j + 48) * 32 + lane], u3, a3);
    }
    float y1 = fmaxf((a0 + a1) + (a2 + a3), 0.0f);

    float b0 = sb2[lane], b1 = 0.f;
#pragma unroll
    for (int j = 0; j < 16; j++) {
        float u0 = __shfl_sync(0xffffffffu, y1, j);
        float u1 = __shfl_sync(0xffffffffu, y1, j + 16);
        b0 = fmaf(sW2[j * 32 + lane],        u0, b0);
        b1 = fmaf(sW2[(j + 16) * 32 + lane], u1, b1);
    }
    float y2 = fmaxf(b0 + b1, 0.0f);

    float p = sW3[lane] * y2;
#pragma unroll
    for (int off = 16; off; off >>= 1)
        p += __shfl_xor_sync(0xffffffffu, p, off);
    if (lane == 0) g_y[row] = p + f3b[0];

    // ---------------- last MLP CTA: softmax + reset ----------------
    __syncthreads();
    if (tid == 0) {
        __threadfence();
        int old = atomicAdd(&g_cnt, 1);
        sLast = (old == 127) ? 1 : 0;
    }
    __syncthreads();

    if (sLast) {
        __threadfence();
        const int wid = tid >> 5;
        float v[4];
        float m = -1e30f;
#pragma unroll
        for (int j = 0; j < 4; j++) {
            v[j] = g_y[tid + 256 * j];
            m = fmaxf(m, v[j]);
        }
#pragma unroll
        for (int off = 16; off; off >>= 1)
            m = fmaxf(m, __shfl_xor_sync(0xffffffffu, m, off));
        if (lane == 0) sred[wid] = m;
        __syncthreads();
        if (wid == 0) {
            float mm = (lane < 8) ? sred[lane] : -1e30f;
#pragma unroll
            for (int off = 16; off; off >>= 1)
                mm = fmaxf(mm, __shfl_xor_sync(0xffffffffu, mm, off));
            if (lane == 0) sbc[0] = mm;
        }
        __syncthreads();
        const float M = sbc[0];

        float e[4];
        float s = 0.0f;
#pragma unroll
        for (int j = 0; j < 4; j++) {
            e[j] = __expf(v[j] - M);
            s += e[j];
        }
#pragma unroll
        for (int off = 16; off; off >>= 1)
            s += __shfl_xor_sync(0xffffffffu, s, off);
        if (lane == 0) sred[wid] = s;
        __syncthreads();
        if (wid == 0) {
            float ss = (lane < 8) ? sred[lane] : 0.0f;
#pragma unroll
            for (int off = 16; off; off >>= 1)
                ss += __shfl_xor_sync(0xffffffffu, ss, off);
            if (lane == 0) sbc[1] = ss;
        }
        __syncthreads();
        const float S = sbc[1];

#pragma unroll
        for (int j = 0; j < 4; j++)
            out[tid + 256 * j] = e[j] / S;

        // reset sync state for next graph replay
        __syncthreads();
        if (tid == 0) { g_flag = 0; g_cnt = 0; }
    }
}

// ============================================================
// launch
// ============================================================
extern "C" void kernel_launch(void* const* d_in, const int* in_sizes, int n_in,
                              void* d_out, int out_size)
{
    const float* x      = (const float*)d_in[0];
    const float* l1_W   = (const float*)d_in[1];
    const float* l1_b   = (const float*)d_in[2];
    const float* g1_Wih = (const float*)d_in[3];
    const float* g1_Whh = (const float*)d_in[4];
    const float* g1_bih = (const float*)d_in[5];
    const float* g1_bhh = (const float*)d_in[6];
    const float* g2_Wih = (const float*)d_in[7];
    const float* g2_Whh = (const float*)d_in[8];
    const float* g2_bih = (const float*)d_in[9];
    const float* g2_bhh = (const float*)d_in[10];
    const float* f1_W   = (const float*)d_in[11];
    const float* f1_b   = (const float*)d_in[12];
    const float* f2_W   = (const float*)d_in[13];
    const float* f2_b   = (const float*)d_in[14];
    const float* f3_W   = (const float*)d_in[15];
    const float* f3_b   = (const float*)d_in[16];

    k_gru1<<<148, 224>>>(x, l1_W, l1_b, g1_Wih, g1_Whh, g1_bih, g1_bhh,
                         g2_Wih, g2_bih, g2_bhh);
    k_tail<<<129, 256>>>(g2_Whh, g2_bhh,
                         f1_W, f1_b, f2_W, f2_b, f3_W, f3_b,
                         (float*)d_out);
}

// round 17
// speedup vs baseline: 1.1320x; 1.0070x over previous
#include <cuda_runtime.h>

#define NN 1024
#define HH 32
typedef unsigned long long u64;
typedef unsigned int u32;

// ---- scratch (no allocations allowed) ----
__device__ float g_h1[NN * HH];                 // GRU1 final hidden per row
__device__ __align__(16) float4 g_gi2[NN * HH]; // packed pre-scaled GRU2 input gates {r,z,n,0}
__device__ float g_h2[HH];                      // GRU2 final hidden
__device__ float g_y[NN];                       // pre-softmax logits
__device__ int   g_flag = 0;                    // GRU2-done flag
__device__ int   g_cnt  = 0;                    // mlp completion counter

// ---- packed f32x2 helpers (sm_100+) ----
__device__ __forceinline__ u64 fma2(u64 a, u64 b, u64 c) {
    u64 d; asm("fma.rn.f32x2 %0, %1, %2, %3;" : "=l"(d) : "l"(a), "l"(b), "l"(c)); return d;
}
__device__ __forceinline__ u64 add2(u64 a, u64 b) {
    u64 d; asm("add.rn.f32x2 %0, %1, %2;" : "=l"(d) : "l"(a), "l"(b)); return d;
}
__device__ __forceinline__ float hadd2(u64 v) {
    float lo, hi; asm("mov.b64 {%0, %1}, %2;" : "=f"(lo), "=f"(hi) : "l"(v)); return lo + hi;
}
__device__ __forceinline__ u64 pack2(float lo, float hi) {
    u64 d; asm("mov.b64 %0, {%1, %2};" : "=l"(d) : "f"(lo), "f"(hi)); return d;
}
__device__ __forceinline__ float tanh_ap(float x) {
    float y; asm("tanh.approx.f32 %0, %1;" : "=f"(y) : "f"(x)); return y;
}
__device__ __forceinline__ u32 smaddr(const void* p) {
    u32 a; asm("{.reg .u64 t; cvta.to.shared.u64 t, %1; cvt.u32.u64 %0, t;}" : "=r"(a) : "l"(p));
    return a;
}
__device__ __forceinline__ void sts_f32(u32 a, float v) {
    asm volatile("st.shared.f32 [%0], %1;" :: "r"(a), "f"(v) : "memory");
}
__device__ __forceinline__ ulonglong2 lds_v2u64(u32 a) {
    ulonglong2 r;
    asm volatile("ld.shared.v2.u64 {%0, %1}, [%2];" : "=l"(r.x), "=l"(r.y) : "r"(a) : "memory");
    return r;
}

// activation forms (scales folded into weights at setup):
//   sigmoid(x) = 0.5 + 0.5*tanh(x/2) -> accumulate x' = 0.5*x (r, z gates)
//   n          = tanh(v)             -> accumulate v at scale 1 (n gate)
#define SRZ 0.5f

// one GRU step — R5 schedule (12 accums, 4-deep, tail adds). Best measured for K1.
__device__ __forceinline__ float gru_step(
    u32 abuf, float h, float ar_s, float az_s, float an_s, float bn_h,
    const u64* Wr, const u64* Wz, const u64* Wn, int lane)
{
    sts_f32(abuf + (lane << 2), h);
    ulonglong2 hA = lds_v2u64(abuf);
    ulonglong2 hB = lds_v2u64(abuf + 16);
    ulonglong2 hC = lds_v2u64(abuf + 32);
    ulonglong2 hD = lds_v2u64(abuf + 48);
    ulonglong2 hE = lds_v2u64(abuf + 64);
    ulonglong2 hF = lds_v2u64(abuf + 80);
    ulonglong2 hG = lds_v2u64(abuf + 96);
    ulonglong2 hH = lds_v2u64(abuf + 112);

    u64 r0, r1, r2, r3, z0, z1, z2, z3, n0, n1, n2, n3;
    r0 = fma2(Wr[0], hA.x, 0);  r1 = fma2(Wr[1], hA.y, 0);
    r2 = fma2(Wr[2], hB.x, 0);  r3 = fma2(Wr[3], hB.y, 0);
    z0 = fma2(Wz[0], hA.x, 0);  z1 = fma2(Wz[1], hA.y, 0);
    z2 = fma2(Wz[2], hB.x, 0);  z3 = fma2(Wz[3], hB.y, 0);
    n0 = fma2(Wn[0], hA.x, 0);  n1 = fma2(Wn[1], hA.y, 0);
    n2 = fma2(Wn[2], hB.x, 0);  n3 = fma2(Wn[3], hB.y, 0);

    r0 = fma2(Wr[4], hC.x, r0); r1 = fma2(Wr[5], hC.y, r1);
    r2 = fma2(Wr[6], hD.x, r2); r3 = fma2(Wr[7], hD.y, r3);
    z0 = fma2(Wz[4], hC.x, z0); z1 = fma2(Wz[5], hC.y, z1);
    z2 = fma2(Wz[6], hD.x, z2); z3 = fma2(Wz[7], hD.y, z3);
    n0 = fma2(Wn[4], hC.x, n0); n1 = fma2(Wn[5], hC.y, n1);
    n2 = fma2(Wn[6], hD.x, n2); n3 = fma2(Wn[7], hD.y, n3);

    r0 = fma2(Wr[8], hE.x, r0);  r1 = fma2(Wr[9], hE.y, r1);
    r2 = fma2(Wr[10], hF.x, r2); r3 = fma2(Wr[11], hF.y, r3);
    z0 = fma2(Wz[8], hE.x, z0);  z1 = fma2(Wz[9], hE.y, z1);
    z2 = fma2(Wz[10], hF.x, z2); z3 = fma2(Wz[11], hF.y, z3);
    n0 = fma2(Wn[8], hE.x, n0);  n1 = fma2(Wn[9], hE.y, n1);
    n2 = fma2(Wn[10], hF.x, n2); n3 = fma2(Wn[11], hF.y, n3);

    r0 = fma2(Wr[12], hG.x, r0); r1 = fma2(Wr[13], hG.y, r1);
    r2 = fma2(Wr[14], hH.x, r2); r3 = fma2(Wr[15], hH.y, r3);
    z0 = fma2(Wz[12], hG.x, z0); z1 = fma2(Wz[13], hG.y, z1);
    z2 = fma2(Wz[14], hH.x, z2); z3 = fma2(Wz[15], hH.y, z3);
    n0 = fma2(Wn[12], hG.x, n0); n1 = fma2(Wn[13], hG.y, n1);
    n2 = fma2(Wn[14], hH.x, n2); n3 = fma2(Wn[15], hH.y, n3);

    float ar = ar_s + hadd2(add2(add2(r0, r1), add2(r2, r3)));
    float az = az_s + hadd2(add2(add2(z0, z1), add2(z2, z3)));
    float hn = bn_h + hadd2(add2(add2(n0, n1), add2(n2, n3)));

    float r  = fmaf(0.5f, tanh_ap(ar), 0.5f);        // sigmoid via tanh
    float z  = fmaf(0.5f, tanh_ap(az), 0.5f);        // sigmoid via tanh
    float nn = tanh_ap(fmaf(r, hn, an_s));           // n gate
    return fmaf(z, h - nn, nn);                      // (1-z)*n + z*h
}

// ============================================================
// K1: GRU1, warp-per-row, 148 CTAs x 7 warps (R5 structure)
// + PDL trigger after all global writes
// ============================================================
__global__ void __launch_bounds__(224, 1) k_gru1(
    const float* __restrict__ x,
    const float* __restrict__ l1W, const float* __restrict__ l1b,
    const float* __restrict__ Wih, const float* __restrict__ Whh,
    const float* __restrict__ bih, const float* __restrict__ bhh,
    const float* __restrict__ Wih2, const float* __restrict__ bih2,
    const float* __restrict__ bhh2)
{
    __shared__ __align__(16) float sh[7][2][32];
    const int warp = threadIdx.x >> 5;
    const int lane = threadIdx.x & 31;
    const int row  = blockIdx.x * 7 + warp;
    if (row >= NN) return;   // early exit counts as trigger for PDL

    u64 Wr[16], Wz[16], Wn[16];
    {
        const float2* wr = (const float2*)(Whh + (0 * HH + lane) * HH);
        const float2* wz = (const float2*)(Whh + (1 * HH + lane) * HH);
        const float2* wn = (const float2*)(Whh + (2 * HH + lane) * HH);
#pragma unroll
        for (int k = 0; k < 16; k++) {
            float2 a = wr[k], b = wz[k], c = wn[k];
            Wr[k] = pack2(a.x * SRZ, a.y * SRZ);
            Wz[k] = pack2(b.x * SRZ, b.y * SRZ);
            Wn[k] = pack2(c.x, c.y);
        }
    }

    // Fold l1 linear into scalar affine input gates: gi[g] = x*A[g] + B[g]
    float Ar = 0.f, Az = 0.f, An = 0.f, Br = 0.f, Bz = 0.f, Bn = 0.f;
#pragma unroll
    for (int j = 0; j < HH; j++) {
        float w = l1W[j], b = l1b[j];
        float wr_ = Wih[(0 * HH + lane) * HH + j];
        float wz_ = Wih[(1 * HH + lane) * HH + j];
        float wn_ = Wih[(2 * HH + lane) * HH + j];
        Ar = fmaf(wr_, w, Ar); Br = fmaf(wr_, b, Br);
        Az = fmaf(wz_, w, Az); Bz = fmaf(wz_, b, Bz);
        An = fmaf(wn_, w, An); Bn = fmaf(wn_, b, Bn);
    }
    Br = (Br + bih[lane]      + bhh[lane])      * SRZ;  Ar *= SRZ;
    Bz = (Bz + bih[32 + lane] + bhh[32 + lane]) * SRZ;  Az *= SRZ;
    Bn = Bn + bih[64 + lane];
    const float bn_h = bhh[64 + lane];

    const u32 shb = smaddr(&sh[warp][0][0]);
    const float* xrow = x + (size_t)row * NN;
    float h = 0.0f;
    float xc = xrow[lane];

    for (int c0 = 0; c0 < NN; c0 += 32) {
        float xcur = xc;
        if (c0 + 32 < NN) xc = xrow[c0 + 32 + lane];
#pragma unroll
        for (int k = 0; k < 32; k++) {
            float xv = __shfl_sync(0xffffffffu, xcur, k);
            float ar_s = fmaf(xv, Ar, Br);
            float az_s = fmaf(xv, Az, Bz);
            float an_s = fmaf(xv, An, Bn);
            h = gru_step(shb + ((k & 1) << 7), h, ar_s, az_s, an_s, bn_h,
                         Wr, Wz, Wn, lane);
        }
    }

    g_h1[row * HH + lane] = h;

    // GRU2 input-gate precompute for time index = row (pre-scaled, packed)
    float a0 = bih2[lane]      + bhh2[lane];
    float a1 = bih2[32 + lane] + bhh2[32 + lane];
    float a2 = bih2[64 + lane];
#pragma unroll
    for (int j = 0; j < HH; j++) {
        float hj = __shfl_sync(0xffffffffu, h, j);
        a0 = fmaf(Wih2[(0 * HH + lane) * HH + j], hj, a0);
        a1 = fmaf(Wih2[(1 * HH + lane) * HH + j], hj, a1);
        a2 = fmaf(Wih2[(2 * HH + lane) * HH + j], hj, a2);
    }
    g_gi2[row * HH + lane] = make_float4(a0 * SRZ, a1 * SRZ, a2, 0.0f);

#if __CUDA_ARCH__ >= 900
    cudaTriggerProgrammaticLaunchCompletion();   // all writes above precede trigger
#endif
}

// ============================================================
// K2 (fused tail, PDL consumer): CTA0 = GRU2 (R12 schedule);
// CTAs 1..128 = MLP; weights staged BEFORE griddepsync so the
// prologue overlaps k_gru1's drain.
// ============================================================
__global__ void __launch_bounds__(256, 1) k_tail(
    const float* __restrict__ Whh2, const float* __restrict__ bhh2,
    const float* __restrict__ f1W, const float* __restrict__ f1b,
    const float* __restrict__ f2W, const float* __restrict__ f2b,
    const float* __restrict__ f3W, const float* __restrict__ f3b,
    float* __restrict__ out)
{
    const int bid  = blockIdx.x;
    const int tid  = threadIdx.x;
    const int lane = tid & 31;

    // ---------------- CTA 0: GRU2 (R12 exact) ----------------
    if (bid == 0) {
        __shared__ __align__(16) float sh[2][32];
        if (tid < 32) {
            u64 Wr[16], Wz[16], Wn[16];
            {
                const float2* wr = (const float2*)(Whh2 + (0 * HH + lane) * HH);
                const float2* wz = (const float2*)(Whh2 + (1 * HH + lane) * HH);
                const float2* wn = (const float2*)(Whh2 + (2 * HH + lane) * HH);
#pragma unroll
                for (int k = 0; k < 16; k++) {
                    float2 a = wr[k], b = wz[k], c = wn[k];
                    Wr[k] = pack2(a.x * SRZ, a.y * SRZ);
                    Wz[k] = pack2(b.x * SRZ, b.y * SRZ);
                    Wn[k] = pack2(c.x, c.y);
                }
            }
            const float bn_h = bhh2[64 + lane];

#if __CUDA_ARCH__ >= 900
            cudaGridDependencySynchronize();   // g_gi2 must be complete
#endif
            float4 pg[4];
#pragma unroll
            for (int i = 0; i < 4; i++)
                pg[i] = g_gi2[i * HH + lane];

            const u32 shb = smaddr(&sh[0][0]);
            float h = 0.0f;
#pragma unroll 4
            for (int t = 0; t < NN; t++) {
                const int s = t & 3;
                const float4 gi = pg[s];
                if (t + 4 < NN)
                    pg[s] = g_gi2[(t + 4) * HH + lane];

                const u32 ab = shb + ((t & 1) << 7);
                sts_f32(ab + (lane << 2), h);
                ulonglong2 hA = lds_v2u64(ab);
                ulonglong2 hB = lds_v2u64(ab + 16);
                ulonglong2 hC = lds_v2u64(ab + 32);
                ulonglong2 hD = lds_v2u64(ab + 48);
                ulonglong2 hE = lds_v2u64(ab + 64);
                ulonglong2 hF = lds_v2u64(ab + 80);
                ulonglong2 hG = lds_v2u64(ab + 96);
                ulonglong2 hH = lds_v2u64(ab + 112);

                // r gate
                u64 r0 = fma2(Wr[0], hA.x, 0),  r1 = fma2(Wr[1], hA.y, 0);
                u64 r2 = fma2(Wr[2], hB.x, 0),  r3 = fma2(Wr[3], hB.y, 0);
                r0 = fma2(Wr[4],  hC.x, r0); r1 = fma2(Wr[5],  hC.y, r1);
                r2 = fma2(Wr[6],  hD.x, r2); r3 = fma2(Wr[7],  hD.y, r3);
                r0 = fma2(Wr[8],  hE.x, r0); r1 = fma2(Wr[9],  hE.y, r1);
                r2 = fma2(Wr[10], hF.x, r2); r3 = fma2(Wr[11], hF.y, r3);
                r0 = fma2(Wr[12], hG.x, r0); r1 = fma2(Wr[13], hG.y, r1);
                r2 = fma2(Wr[14], hH.x, r2); r3 = fma2(Wr[15], hH.y, r3);
                float ar = gi.x + hadd2(add2(add2(r0, r1), add2(r2, r3)));
                float r  = fmaf(0.5f, tanh_ap(ar), 0.5f);

                // z gate
                u64 z0 = fma2(Wz[0], hA.x, 0),  z1 = fma2(Wz[1], hA.y, 0);
                u64 z2 = fma2(Wz[2], hB.x, 0),  z3 = fma2(Wz[3], hB.y, 0);
                z0 = fma2(Wz[4],  hC.x, z0); z1 = fma2(Wz[5],  hC.y, z1);
                z2 = fma2(Wz[6],  hD.x, z2); z3 = fma2(Wz[7],  hD.y, z3);
                z0 = fma2(Wz[8],  hE.x, z0); z1 = fma2(Wz[9],  hE.y, z1);
                z2 = fma2(Wz[10], hF.x, z2); z3 = fma2(Wz[11], hF.y, z3);
                z0 = fma2(Wz[12], hG.x, z0); z1 = fma2(Wz[13], hG.y, z1);
                z2 = fma2(Wz[14], hH.x, z2); z3 = fma2(Wz[15], hH.y, z3);
                float az = gi.y + hadd2(add2(add2(z0, z1), add2(z2, z3)));
                float z  = fmaf(0.5f, tanh_ap(az), 0.5f);

                // n gate
                u64 n0 = fma2(Wn[0], hA.x, 0),  n1 = fma2(Wn[1], hA.y, 0);
                u64 n2 = fma2(Wn[2], hB.x, 0),  n3 = fma2(Wn[3], hB.y, 0);
                n0 = fma2(Wn[4],  hC.x, n0); n1 = fma2(Wn[5],  hC.y, n1);
                n2 = fma2(Wn[6],  hD.x, n2); n3 = fma2(Wn[7],  hD.y, n3);
                n0 = fma2(Wn[8],  hE.x, n0); n1 = fma2(Wn[9],  hE.y, n1);
                n2 = fma2(Wn[10], hF.x, n2); n3 = fma2(Wn[11], hF.y, n3);
                n0 = fma2(Wn[12], hG.x, n0); n1 = fma2(Wn[13], hG.y, n1);
                n2 = fma2(Wn[14], hH.x, n2); n3 = fma2(Wn[15], hH.y, n3);
                float hn = bn_h + hadd2(add2(add2(n0, n1), add2(n2, n3)));
                float nn = tanh_ap(fmaf(r, hn, gi.z));

                h = fmaf(z, h - nn, nn);
            }
            g_h2[lane] = h;
        }
        __syncthreads();
        if (tid == 0) {
            __threadfence();
            atomicExch(&g_flag, 1);
        }
        return;
    }

    // ---------------- CTAs 1..128: MLP ----------------
    __shared__ float sW1[64 * 32];
    __shared__ float sW2[32 * 32];
    __shared__ float sb1[32], sb2[32], sW3[32];
    __shared__ int sLast;
    __shared__ float sred[8], sbc[2];

    const int row = (bid - 1) * 8 + (tid >> 5);

    // weight staging overlaps k_gru1's drain (pre-griddepsync)
    for (int idx = tid; idx < 2048; idx += 256) {
        int i = idx >> 6, j = idx & 63;
        sW1[j * 32 + i] = f1W[idx];
    }
    for (int idx = tid; idx < 1024; idx += 256) {
        int i = idx >> 5, j = idx & 31;
        sW2[j * 32 + i] = f2W[idx];
    }
    if (tid < 32) { sb1[tid] = f1b[tid]; sb2[tid] = f2b[tid]; sW3[tid] = f3W[tid]; }

#if __CUDA_ARCH__ >= 900
    cudaGridDependencySynchronize();   // g_h1 must be complete
#endif

    float hl = g_h1[row * HH + lane];
    __syncthreads();

    // layer-1 partial from hl (independent of gru2)
    float a0 = 0.f, a1 = 0.f;
#pragma unroll
    for (int j = 0; j < 16; j++) {
        float u0 = __shfl_sync(0xffffffffu, hl, j);
        float u1 = __shfl_sync(0xffffffffu, hl, j + 16);
        a0 = fmaf(sW1[j * 32 + lane],        u0, a0);
        a1 = fmaf(sW1[(j + 16) * 32 + lane], u1, a1);
    }

    // wait for gru2
    if (tid == 0) {
        while (*((volatile int*)&g_flag) == 0) __nanosleep(64);
        __threadfence();
    }
    __syncthreads();

    float hg = g_h2[lane];
    float a2 = sb1[lane], a3 = 0.f;
#pragma unroll
    for (int j = 0; j < 16; j++) {
        float u2 = __shfl_sync(0xffffffffu, hg, j);
        float u3 = __shfl_sync(0xffffffffu, hg, j + 16);
        a2 = fmaf(sW1[(j + 32) * 32 + lane], u2, a2);
        a3 = fmaf(sW1[(j + 48) * 32 + lane], u3, a3);
    }
    float y1 = fmaxf((a0 + a1) + (a2 + a3), 0.0f);

    float b0 = sb2[lane], b1 = 0.f;
#pragma unroll
    for (int j = 0; j < 16; j++) {
        float u0 = __shfl_sync(0xffffffffu, y1, j);
        float u1 = __shfl_sync(0xffffffffu, y1, j + 16);
        b0 = fmaf(sW2[j * 32 + lane],        u0, b0);
        b1 = fmaf(sW2[(j + 16) * 32 + lane], u1, b1);
    }
    float y2 = fmaxf(b0 + b1, 0.0f);

    float p = sW3[lane] * y2;
#pragma unroll
    for (int off = 16; off; off >>= 1)
        p += __shfl_xor_sync(0xffffffffu, p, off);
    if (lane == 0) g_y[row] = p + f3b[0];

    // ---------------- last MLP CTA: softmax + reset ----------------
    __syncthreads();
    if (tid == 0) {
        __threadfence();
        int old = atomicAdd(&g_cnt, 1);
        sLast = (old == 127) ? 1 : 0;
    }
    __syncthreads();

    if (sLast) {
        __threadfence();
        const int wid = tid >> 5;
        float v[4];
        float m = -1e30f;
#pragma unroll
        for (int j = 0; j < 4; j++) {
            v[j] = g_y[tid + 256 * j];
            m = fmaxf(m, v[j]);
        }
#pragma unroll
        for (int off = 16; off; off >>= 1)
            m = fmaxf(m, __shfl_xor_sync(0xffffffffu, m, off));
        if (lane == 0) sred[wid] = m;
        __syncthreads();
        if (wid == 0) {
            float mm = (lane < 8) ? sred[lane] : -1e30f;
#pragma unroll
            for (int off = 16; off; off >>= 1)
                mm = fmaxf(mm, __shfl_xor_sync(0xffffffffu, mm, off));
            if (lane == 0) sbc[0] = mm;
        }
        __syncthreads();
        const float M = sbc[0];

        float e[4];
        float s = 0.0f;
#pragma unroll
        for (int j = 0; j < 4; j++) {
            e[j] = __expf(v[j] - M);
            s += e[j];
        }
#pragma unroll
        for (int off = 16; off; off >>= 1)
            s += __shfl_xor_sync(0xffffffffu, s, off);
        if (lane == 0) sred[wid] = s;
        __syncthreads();
        if (wid == 0) {
            float ss = (lane < 8) ? sred[lane] : 0.0f;
#pragma unroll
            for (int off = 16; off; off >>= 1)
                ss += __shfl_xor_sync(0xffffffffu, ss, off);
            if (lane == 0) sbc[1] = ss;
        }
        __syncthreads();
        const float S = sbc[1];

#pragma unroll
        for (int j = 0; j < 4; j++)
            out[tid + 256 * j] = e[j] / S;

        // reset sync state for next graph replay
        __syncthreads();
        if (tid == 0) { g_flag = 0; g_cnt = 0; }
    }
}

// ============================================================
// launch — k_tail launched with PDL so its prologue overlaps
// k_gru1's drain
// ============================================================
extern "C" void kernel_launch(void* const* d_in, const int* in_sizes, int n_in,
                              void* d_out, int out_size)
{
    const float* x      = (const float*)d_in[0];
    const float* l1_W   = (const float*)d_in[1];
    const float* l1_b   = (const float*)d_in[2];
    const float* g1_Wih = (const float*)d_in[3];
    const float* g1_Whh = (const float*)d_in[4];
    const float* g1_bih = (const float*)d_in[5];
    const float* g1_bhh = (const float*)d_in[6];
    const float* g2_Wih = (const float*)d_in[7];
    const float* g2_Whh = (const float*)d_in[8];
    const float* g2_bih = (const float*)d_in[9];
    const float* g2_bhh = (const float*)d_in[10];
    const float* f1_W   = (const float*)d_in[11];
    const float* f1_b   = (const float*)d_in[12];
    const float* f2_W   = (const float*)d_in[13];
    const float* f2_b   = (const float*)d_in[14];
    const float* f3_W   = (const float*)d_in[15];
    const float* f3_b   = (const float*)d_in[16];

    k_gru1<<<148, 224>>>(x, l1_W, l1_b, g1_Wih, g1_Whh, g1_bih, g1_bhh,
                         g2_Wih, g2_bih, g2_bhh);

    cudaLaunchConfig_t cfg = {};
    cfg.gridDim  = dim3(129, 1, 1);
    cfg.blockDim = dim3(256, 1, 1);
    cfg.dynamicSmemBytes = 0;
    cudaLaunchAttribute attrs[1];
    attrs[0].id = cudaLaunchAttributeProgrammaticStreamSerialization;
    attrs[0].val.programmaticStreamSerializationAllowed = 1;
    cfg.attrs = attrs;
    cfg.numAttrs = 1;
    cudaLaunchKernelEx(&cfg, k_tail,
                       g2_Whh, g2_bhh,
                       f1_W, f1_b, f2_W, f2_b, f3_W, f3_b,
                       (float*)d_out);
}